// round 15
// baseline (speedup 1.0000x reference)
#include <cuda_runtime.h>
#include <stdint.h>

#define GS 128            // grid dim
#define VX 132            // vol8 x-stride (padded from 129; 33 words)
#define VY 129
#define VZ 129
#define VTOT (VZ*VY*VX)   // 2,196,612 bytes
#define BBT 512           // build block threads

// Packed neighborhood volume: byte at (z,y,x) holds bits of
// grid[z-1+dz][y-1+dy][x-1+dx] (0 if OOB) at bit dz*4+dy*2+dx.
__device__ uint8_t g_vol8[VTOT];

// ---- Fused build: one 512-thread block per vol8 z-plane ----
// 512 threads (not 1024) halves the per-SM footprint so more sample blocks
// co-reside and prefetch behind the PDL release.
__global__ void __launch_bounds__(BBT)
fused_build_kernel(const float4* __restrict__ grid4) {
    asm volatile("griddepcontrol.launch_dependents;");

    int z = blockIdx.x;                 // 0..128
    // bits[p][r][w]: bit i of word w = grid[z-1+p][r-1][32w+i] (0 if OOB)
    __shared__ uint32_t bits[2][130][4];
    int tid = threadIdx.x;

    for (int i = tid; i < 2 * 130 * 4; i += BBT)
        ((uint32_t*)bits)[i] = 0;       // covers OOB boundary rows 0,129
    __syncthreads();

    // pack: 2 planes x 128 rows x 32 float4 = 8192 tasks, 16/thread,
    // in two MLP-8 batches (load 8, consume 8).
#pragma unroll
    for (int half = 0; half < 2; ++half) {
        float4 v[8];
#pragma unroll
        for (int it = 0; it < 8; ++it) {
            int idx = (half * 8 + it) * BBT + tid;
            int p   = idx >> 12;
            int rem = idx & 4095;
            int gz  = z - 1 + p;
            if (gz >= 0 && gz < GS)
                v[it] = __ldg(&grid4[gz * 4096 + rem]);   // rem = r*32 + q
            else
                v[it] = make_float4(0.0f, 0.0f, 0.0f, 0.0f);
        }
#pragma unroll
        for (int it = 0; it < 8; ++it) {
            int idx = (half * 8 + it) * BBT + tid;
            int p   = idx >> 12;
            int rem = idx & 4095;
            int r   = rem >> 5;          // grid row 0..127
            int q   = rem & 31;          // float4 within row
            unsigned nib = (v[it].x != 0.0f ? 1u : 0u)
                         | (v[it].y != 0.0f ? 2u : 0u)
                         | (v[it].z != 0.0f ? 4u : 0u)
                         | (v[it].w != 0.0f ? 8u : 0u);
            unsigned word = nib << (4 * (tid & 7));
            word |= __shfl_xor_sync(0xffffffffu, word, 1);
            word |= __shfl_xor_sync(0xffffffffu, word, 2);
            word |= __shfl_xor_sync(0xffffffffu, word, 4);
            if ((tid & 7) == 0) bits[p][r + 1][q >> 3] = word;
        }
    }
    __syncthreads();

    // emit: 129 rows x 5 chunks = 645 tasks (two strided passes);
    // chunk 4 writes only 1 word (x=128..131 pad) to stay inside the row.
    for (int t = tid; t < VY * 5; t += BBT) {
        int c  = t % 5;
        int rl = t / 5;                 // vol8 y
        uint64_t v64[4];
#pragma unroll
        for (int dz = 0; dz < 2; ++dz) {
#pragma unroll
            for (int dy = 0; dy < 2; ++dy) {
                uint32_t lo = (c > 0) ? bits[dz][rl + dy][c - 1] : 0u;
                uint32_t hi = (c < 4) ? bits[dz][rl + dy][c]     : 0u;
                v64[dz * 2 + dy] = ((uint64_t)hi << 32) | (uint64_t)lo;
            }
        }
        int nw = (c == 4) ? 1 : 8;
        uint32_t* dst = (uint32_t*)&g_vol8[(size_t)(z * VY + rl) * VX + 32 * c];
#pragma unroll
        for (int w = 0; w < 8; ++w) {
            if (w >= nw) break;
            uint32_t acc = 0;
#pragma unroll
            for (int j = 0; j < 4; ++j) {
                int k = w * 4 + j;
                unsigned byte = 0;
#pragma unroll
                for (int e = 0; e < 4; ++e)
                    byte |= (unsigned)((v64[e] >> (31 + k)) & 3ull) << (2 * e);
                acc |= byte << (8 * j);
            }
            dst[w] = acc;
        }
    }
}

// ---- Sample (R14 exact: proven best) ----
__device__ __forceinline__ void coord_prep(float x, float y, float z,
                                           int& idx, float& wx, float& wy, float& wz) {
    // ((x+1)*128 - 1) * 0.5 -> fma(x, 64, 63.5)
    float ix = fmaf(x, 64.0f, 63.5f);
    float iy = fmaf(y, 64.0f, 63.5f);
    float iz = fmaf(z, 64.0f, 63.5f);
    float fx = floorf(ix), fy = floorf(iy), fz = floorf(iz);
    wx = ix - fx; wy = iy - fy; wz = iz - fz;
    int ix0 = (int)fx, iy0 = (int)fy, iz0 = (int)fz;
    // coords in [-1,1] guarantee base in [-1,127]; single composite clamp
    // for memory safety only (value-neutral for in-range inputs).
    idx = ((iz0 + 1) * VY + (iy0 + 1)) * VX + (ix0 + 1);
    idx = min(VTOT - 1, max(0, idx));
}

__device__ __forceinline__ float lerp_byte(unsigned b, float wx, float wy, float wz) {
    float f0 = (float)( b       & 1u);
    float f1 = (float)((b >> 1) & 1u);
    float f2 = (float)((b >> 2) & 1u);
    float f3 = (float)((b >> 3) & 1u);
    float f4 = (float)((b >> 4) & 1u);
    float f5 = (float)((b >> 5) & 1u);
    float f6 = (float)((b >> 6) & 1u);
    float f7 = (float)((b >> 7) & 1u);
    float c00 = fmaf(wx, f1 - f0, f0);
    float c10 = fmaf(wx, f3 - f2, f2);
    float c01 = fmaf(wx, f5 - f4, f4);
    float c11 = fmaf(wx, f7 - f6, f6);
    float c0  = fmaf(wy, c10 - c00, c00);
    float c1  = fmaf(wy, c11 - c01, c01);
    return fmaf(wz, c1 - c0, c0);
}

// 4 points per thread. Everything vol8-independent (coord loads + all index/
// weight math) runs BEFORE the PDL wait; only gathers+lerp+store follow it.
// Grid is exactly n4/256 blocks (n4 % 256 == 0), so no bounds guard needed.
__global__ void sample_kernel(const float4* __restrict__ coords4,
                              float4* __restrict__ out4, int n4) {
    int tid = blockIdx.x * blockDim.x + threadIdx.x;
    float4 a = __ldcs(&coords4[(size_t)tid * 3 + 0]);
    float4 b = __ldcs(&coords4[(size_t)tid * 3 + 1]);
    float4 c = __ldcs(&coords4[(size_t)tid * 3 + 2]);

    int   i0, i1, i2, i3;
    float wx0, wy0, wz0, wx1, wy1, wz1, wx2, wy2, wz2, wx3, wy3, wz3;
    coord_prep(a.x, a.y, a.z, i0, wx0, wy0, wz0);
    coord_prep(a.w, b.x, b.y, i1, wx1, wy1, wz1);
    coord_prep(b.z, b.w, c.x, i2, wx2, wy2, wz2);
    coord_prep(c.y, c.z, c.w, i3, wx3, wy3, wz3);

    // Wait for the build grid's memory to be visible (no-op without PDL).
    asm volatile("griddepcontrol.wait;" ::: "memory");

    float4 o;
    o.x = lerp_byte((unsigned)__ldg(&g_vol8[i0]), wx0, wy0, wz0);
    o.y = lerp_byte((unsigned)__ldg(&g_vol8[i1]), wx1, wy1, wz1);
    o.z = lerp_byte((unsigned)__ldg(&g_vol8[i2]), wx2, wy2, wz2);
    o.w = lerp_byte((unsigned)__ldg(&g_vol8[i3]), wx3, wy3, wz3);
    __stcs(&out4[tid], o);
}

extern "C" void kernel_launch(void* const* d_in, const int* in_sizes, int n_in,
                              void* d_out, int out_size) {
    const float* grid   = (const float*)d_in[0];   // 128^3 floats
    const float* coords = (const float*)d_in[1];   // N*3 floats
    float* out = (float*)d_out;                    // N floats

    // 1) fused build (releases dependent launch at block start)
    fused_build_kernel<<<VZ, BBT>>>((const float4*)grid);

    // 2) sample, launched as a programmatic dependent of the build
    int n  = in_sizes[1] / 3;                      // 8,388,608
    int n4 = n / 4;                                // 2,097,152 (256-divisible)

    cudaLaunchConfig_t cfg = {};
    cfg.gridDim  = dim3(n4 / 256, 1, 1);
    cfg.blockDim = dim3(256, 1, 1);
    cfg.dynamicSmemBytes = 0;
    cfg.stream = 0;                                // same (legacy) stream
    cudaLaunchAttribute attr[1];
    attr[0].id = cudaLaunchAttributeProgrammaticStreamSerialization;
    attr[0].val.programmaticStreamSerializationAllowed = 1;
    cfg.attrs = attr;
    cfg.numAttrs = 1;
    cudaLaunchKernelEx(&cfg, sample_kernel,
                       (const float4*)coords, (float4*)out, n4);
}

// round 16
// speedup vs baseline: 1.0477x; 1.0477x over previous
#include <cuda_runtime.h>
#include <stdint.h>

#define GS 128            // grid dim
#define VX 132            // vol8 x-stride (padded from 129; 33 words)
#define VY 129
#define VZ 129
#define VTOT (VZ*VY*VX)   // 2,196,612 bytes

// Packed neighborhood volume: byte at (z,y,x) holds bits of
// grid[z-1+dz][y-1+dy][x-1+dx] (0 if OOB) at bit dz*4+dy*2+dx.
__device__ uint8_t g_vol8[VTOT];

// ---- Fused build: one 1024-thread block per vol8 z-plane ----
// First instruction releases the dependent sample launch (PDL): sample blocks
// start streaming coords + computing indices while we build.
__global__ void __launch_bounds__(1024)
fused_build_kernel(const float4* __restrict__ grid4) {
    asm volatile("griddepcontrol.launch_dependents;");

    int z = blockIdx.x;                 // 0..128
    // bits[p][r][w]: bit i of word w = grid[z-1+p][r-1][32w+i] (0 if OOB)
    __shared__ uint32_t bits[2][130][4];
    int tid = threadIdx.x;

    if (tid < 2 * 130 * 4) ((uint32_t*)bits)[tid] = 0;  // OOB rows 0,129
    __syncthreads();

    // pack: 2 planes x 128 rows x 32 float4 = 8192 tasks, 8/thread, MLP=8
    float4 v[8];
#pragma unroll
    for (int it = 0; it < 8; ++it) {
        int idx = it * 1024 + tid;
        int p   = idx >> 12;
        int rem = idx & 4095;
        int gz  = z - 1 + p;
        if (gz >= 0 && gz < GS)
            v[it] = __ldg(&grid4[gz * 4096 + rem]);   // rem = r*32 + q
        else
            v[it] = make_float4(0.0f, 0.0f, 0.0f, 0.0f);
    }
#pragma unroll
    for (int it = 0; it < 8; ++it) {
        int idx = it * 1024 + tid;
        int p   = idx >> 12;
        int rem = idx & 4095;
        int r   = rem >> 5;             // grid row 0..127
        int q   = rem & 31;             // float4 within row
        unsigned nib = (v[it].x != 0.0f ? 1u : 0u)
                     | (v[it].y != 0.0f ? 2u : 0u)
                     | (v[it].z != 0.0f ? 4u : 0u)
                     | (v[it].w != 0.0f ? 8u : 0u);
        unsigned word = nib << (4 * (tid & 7));
        word |= __shfl_xor_sync(0xffffffffu, word, 1);
        word |= __shfl_xor_sync(0xffffffffu, word, 2);
        word |= __shfl_xor_sync(0xffffffffu, word, 4);
        if ((tid & 7) == 0) bits[p][r + 1][q >> 3] = word;
    }
    __syncthreads();

    // emit: 129 rows x 5 chunks; chunk 4 writes only 1 word (x=128..131 pad)
    // to stay inside the padded row.
    if (tid < VY * 5) {
        int c  = tid % 5;
        int rl = tid / 5;               // vol8 y
        uint64_t v64[4];
#pragma unroll
        for (int dz = 0; dz < 2; ++dz) {
#pragma unroll
            for (int dy = 0; dy < 2; ++dy) {
                uint32_t lo = (c > 0) ? bits[dz][rl + dy][c - 1] : 0u;
                uint32_t hi = (c < 4) ? bits[dz][rl + dy][c]     : 0u;
                v64[dz * 2 + dy] = ((uint64_t)hi << 32) | (uint64_t)lo;
            }
        }
        int nw = (c == 4) ? 1 : 8;
        uint32_t* dst = (uint32_t*)&g_vol8[(size_t)(z * VY + rl) * VX + 32 * c];
#pragma unroll
        for (int w = 0; w < 8; ++w) {
            if (w >= nw) break;
            uint32_t acc = 0;
#pragma unroll
            for (int j = 0; j < 4; ++j) {
                int k = w * 4 + j;
                unsigned byte = 0;
#pragma unroll
                for (int e = 0; e < 4; ++e)
                    byte |= (unsigned)((v64[e] >> (31 + k)) & 3ull) << (2 * e);
                acc |= byte << (8 * j);
            }
            dst[w] = acc;
        }
    }
}

// ---- Sample ----
__device__ __forceinline__ void coord_prep(float x, float y, float z,
                                           int& idx, float& wx, float& wy, float& wz) {
    // ((x+1)*128 - 1) * 0.5 -> fma(x, 64, 63.5)
    float ix = fmaf(x, 64.0f, 63.5f);
    float iy = fmaf(y, 64.0f, 63.5f);
    float iz = fmaf(z, 64.0f, 63.5f);
    float fx = floorf(ix), fy = floorf(iy), fz = floorf(iz);
    wx = ix - fx; wy = iy - fy; wz = iz - fz;
    int ix0 = (int)fx, iy0 = (int)fy, iz0 = (int)fz;
    // coords in [-1,1] guarantee base in [-1,127]; single composite clamp
    // for memory safety only (value-neutral for in-range inputs).
    idx = ((iz0 + 1) * VY + (iy0 + 1)) * VX + (ix0 + 1);
    idx = min(VTOT - 1, max(0, idx));
}

__device__ __forceinline__ float lerp_byte(unsigned b, float wx, float wy, float wz) {
    float f0 = (float)( b       & 1u);
    float f1 = (float)((b >> 1) & 1u);
    float f2 = (float)((b >> 2) & 1u);
    float f3 = (float)((b >> 3) & 1u);
    float f4 = (float)((b >> 4) & 1u);
    float f5 = (float)((b >> 5) & 1u);
    float f6 = (float)((b >> 6) & 1u);
    float f7 = (float)((b >> 7) & 1u);
    float c00 = fmaf(wx, f1 - f0, f0);
    float c10 = fmaf(wx, f3 - f2, f2);
    float c01 = fmaf(wx, f5 - f4, f4);
    float c11 = fmaf(wx, f7 - f6, f6);
    float c0  = fmaf(wy, c10 - c00, c00);
    float c1  = fmaf(wy, c11 - c01, c01);
    return fmaf(wz, c1 - c0, c0);
}

// 4 points per thread. Everything vol8-independent (coord loads + all index/
// weight math) runs BEFORE the PDL wait; only gathers+lerp+store follow it.
// Grid is exactly n4/256 blocks (n4 % 256 == 0), so no bounds guard needed.
__global__ void sample_kernel(const float4* __restrict__ coords4,
                              float4* __restrict__ out4, int n4) {
    int tid = blockIdx.x * blockDim.x + threadIdx.x;
    float4 a = __ldcs(&coords4[(size_t)tid * 3 + 0]);
    float4 b = __ldcs(&coords4[(size_t)tid * 3 + 1]);
    float4 c = __ldcs(&coords4[(size_t)tid * 3 + 2]);

    int   i0, i1, i2, i3;
    float wx0, wy0, wz0, wx1, wy1, wz1, wx2, wy2, wz2, wx3, wy3, wz3;
    coord_prep(a.x, a.y, a.z, i0, wx0, wy0, wz0);
    coord_prep(a.w, b.x, b.y, i1, wx1, wy1, wz1);
    coord_prep(b.z, b.w, c.x, i2, wx2, wy2, wz2);
    coord_prep(c.y, c.z, c.w, i3, wx3, wy3, wz3);

    // Wait for the build grid's memory to be visible (no-op without PDL).
    asm volatile("griddepcontrol.wait;" ::: "memory");

    float4 o;
    o.x = lerp_byte((unsigned)__ldg(&g_vol8[i0]), wx0, wy0, wz0);
    o.y = lerp_byte((unsigned)__ldg(&g_vol8[i1]), wx1, wy1, wz1);
    o.z = lerp_byte((unsigned)__ldg(&g_vol8[i2]), wx2, wy2, wz2);
    o.w = lerp_byte((unsigned)__ldg(&g_vol8[i3]), wx3, wy3, wz3);
    __stcs(&out4[tid], o);
}

extern "C" void kernel_launch(void* const* d_in, const int* in_sizes, int n_in,
                              void* d_out, int out_size) {
    const float* grid   = (const float*)d_in[0];   // 128^3 floats
    const float* coords = (const float*)d_in[1];   // N*3 floats
    float* out = (float*)d_out;                    // N floats

    // 1) fused build (releases dependent launch at block start)
    fused_build_kernel<<<VZ, 1024>>>((const float4*)grid);

    // 2) sample, launched as a programmatic dependent of the build
    int n  = in_sizes[1] / 3;                      // 8,388,608
    int n4 = n / 4;                                // 2,097,152 (256-divisible)

    cudaLaunchConfig_t cfg = {};
    cfg.gridDim  = dim3(n4 / 256, 1, 1);
    cfg.blockDim = dim3(256, 1, 1);
    cfg.dynamicSmemBytes = 0;
    cfg.stream = 0;                                // same (legacy) stream
    cudaLaunchAttribute attr[1];
    attr[0].id = cudaLaunchAttributeProgrammaticStreamSerialization;
    attr[0].val.programmaticStreamSerializationAllowed = 1;
    cfg.attrs = attr;
    cfg.numAttrs = 1;
    cudaLaunchKernelEx(&cfg, sample_kernel,
                       (const float4*)coords, (float4*)out, n4);
}